// round 4
// baseline (speedup 1.0000x reference)
#include <cuda_runtime.h>
#include <math.h>

// Problem constants
#define Bsz  64
#define Tlen 256
#define Din  1024
#define Hdim 1024
#define Lnum 4
#define Odim 512
#define NBLK 128   // persistent blocks (<=148 SMs -> all co-resident, spin barrier safe)

// Persistent state (device globals — no allocation allowed).
// h double-buffered by timestep parity: at step t (p=t&1) layers read
// g_h[p][l] (h_{t-1}) and write g_h[p^1][l] (h_t). Layer l>0 reads its input
// from g_h[p^1][l-1], produced earlier in the same timestep (grid barrier).
__device__ float g_h[2][Lnum][Bsz * Hdim];   // 2 MB
__device__ float g_c[Lnum][Bsz * Hdim];      // 1 MB

// Software grid barrier state. g_gen only ever increases (safe across graph
// replays); g_count returns to 0 at the end of every barrier episode.
__device__ volatile unsigned g_gen = 0;
__device__ unsigned g_count = 0;

__device__ __forceinline__ void grid_sync() {
    __syncthreads();
    if (threadIdx.x == 0) {
        __threadfence();
        unsigned my = g_gen;                    // read BEFORE arriving
        if (atomicAdd(&g_count, 1u) == NBLK - 1) {
            g_count = 0;
            __threadfence();
            g_gen = my + 1;                     // release
        } else {
            while (g_gen == my) { __nanosleep(40); }
        }
        __threadfence();
    }
    __syncthreads();
}

union U64 { unsigned long long u; float2 f; };

// Packed fp32x2 FMA (SASS FFMA2) — 2 exact fp32 FMAs per instruction.
__device__ __forceinline__ unsigned long long dup2(float a) {
    unsigned long long r;
    asm("mov.b64 %0, {%1, %1};" : "=l"(r) : "f"(a));
    return r;
}
__device__ __forceinline__ void fma2(unsigned long long &d,
                                     unsigned long long a,
                                     unsigned long long b) {
    asm("fma.rn.f32x2 %0, %1, %2, %0;" : "+l"(d) : "l"(a), "l"(b));
}

__global__ void zero_state() {
    int i = blockIdx.x * blockDim.x + threadIdx.x;
    (&g_h[0][0][0])[i] = 0.f;                 // 2*L*B*H = 524288 floats, exact
    if (i < Lnum * Bsz * Hdim)
        (&g_c[0][0])[i] = 0.f;
}

// Persistent LSTM kernel. 128 blocks x 256 threads.
// Each block owns 8 hidden units (32 gate columns) for ALL (t, layer) steps.
// Warp-group split: threads [0,128) compute the x@Wih^T partial gates,
// threads [128,256) compute h@Whh^T; partials are summed in smem (Gs).
// Each half-thread computes a 4x4 micro-tile of its 64x32 partial.
__global__ __launch_bounds__(256, 1) void lstm_persistent(
    const float* __restrict__ x,
    const float* __restrict__ Wih, const float* __restrict__ Whh,
    const float* __restrict__ bih, const float* __restrict__ bhh)
{
    __shared__ float As[2][32][65];  // [half][k][m], padded (transpose store)
    __shared__ float Ws[2][32][34];  // [half][k][n], padded, 8B-aligned rows
    __shared__ float Gs[64][33];     // gate exchange / partial accumulation
    __shared__ float bias_s[Lnum][32];

    const int tid   = threadIdx.x;
    const int half  = tid >> 7;          // 0: x-phase, 1: h-phase
    const int tid_h = tid & 127;
    const int n0    = blockIdx.x * 8;    // first hidden unit of this block

    // Preload all layers' combined biases (32 gate cols per block, 4 layers)
    if (tid < Lnum * 32) {
        int l = tid >> 5, col = tid & 31;
        int gate = col >> 3, hid = n0 + (col & 7);
        int row  = l * 4 * Hdim + gate * Hdim + hid;
        bias_s[l][col] = bih[row] + bhh[row];
    }

    const int kq  = tid_h & 7;    // float4 chunk within k-tile
    const int mr  = tid_h >> 3;   // 0..15
    const int ty4 = mr * 4;       // output rows ty4..ty4+3
    const int tx4 = kq * 4;       // output cols tx4..tx4+3

    // W rows this thread fetches (tile cols n = mr and mr+16)
    const int nA = mr, nB = mr + 16;
    const int wrow0 = (nA >> 3) * Hdim + n0 + (nA & 7);
    const int wrow1 = (nB >> 3) * Hdim + n0 + (nB & 7);

    __syncthreads();   // bias_s ready

    for (int t = 0; t < Tlen; ++t) {
        const int p = t & 1;
        for (int l = 0; l < Lnum; ++l) {
            // --- per-half operand selection ---
            const float* A; int as; const float* W;
            if (half == 0) {
                if (l == 0) { A = x + (size_t)t * Din; as = Tlen * Din; }
                else        { A = g_h[p ^ 1][l - 1];   as = Hdim; }
                W = Wih + (size_t)l * 4 * Hdim * Din;
            } else {
                A = g_h[p][l]; as = Hdim;
                W = Whh + (size_t)l * 4 * Hdim * Hdim;
            }
            float*       hout = g_h[p ^ 1][l];
            float*       cptr = g_c[l];

            U64 acc[4][2];
            #pragma unroll
            for (int r = 0; r < 4; ++r) {
                acc[r][0].f = make_float2(0.f, 0.f);
                acc[r][1].f = make_float2(0.f, 0.f);
            }

            // Prefetch first k-tile
            float4 pa0 = *(const float4*)(A + (size_t)(mr     ) * as + tx4);
            float4 pa1 = *(const float4*)(A + (size_t)(mr + 16) * as + tx4);
            float4 pa2 = *(const float4*)(A + (size_t)(mr + 32) * as + tx4);
            float4 pa3 = *(const float4*)(A + (size_t)(mr + 48) * as + tx4);
            float4 pw0 = *(const float4*)(W + (size_t)wrow0 * 1024 + tx4);
            float4 pw1 = *(const float4*)(W + (size_t)wrow1 * 1024 + tx4);

            for (int k0 = 0; k0 < 1024; k0 += 32) {
                __syncthreads();
                As[half][tx4 + 0][mr     ] = pa0.x; As[half][tx4 + 1][mr     ] = pa0.y;
                As[half][tx4 + 2][mr     ] = pa0.z; As[half][tx4 + 3][mr     ] = pa0.w;
                As[half][tx4 + 0][mr + 16] = pa1.x; As[half][tx4 + 1][mr + 16] = pa1.y;
                As[half][tx4 + 2][mr + 16] = pa1.z; As[half][tx4 + 3][mr + 16] = pa1.w;
                As[half][tx4 + 0][mr + 32] = pa2.x; As[half][tx4 + 1][mr + 32] = pa2.y;
                As[half][tx4 + 2][mr + 32] = pa2.z; As[half][tx4 + 3][mr + 32] = pa2.w;
                As[half][tx4 + 0][mr + 48] = pa3.x; As[half][tx4 + 1][mr + 48] = pa3.y;
                As[half][tx4 + 2][mr + 48] = pa3.z; As[half][tx4 + 3][mr + 48] = pa3.w;
                Ws[half][tx4 + 0][nA] = pw0.x; Ws[half][tx4 + 1][nA] = pw0.y;
                Ws[half][tx4 + 2][nA] = pw0.z; Ws[half][tx4 + 3][nA] = pw0.w;
                Ws[half][tx4 + 0][nB] = pw1.x; Ws[half][tx4 + 1][nB] = pw1.y;
                Ws[half][tx4 + 2][nB] = pw1.z; Ws[half][tx4 + 3][nB] = pw1.w;
                __syncthreads();

                // Prefetch next k-tile while computing this one
                int k1 = k0 + 32;
                if (k1 < 1024) {
                    pa0 = *(const float4*)(A + (size_t)(mr     ) * as + k1 + tx4);
                    pa1 = *(const float4*)(A + (size_t)(mr + 16) * as + k1 + tx4);
                    pa2 = *(const float4*)(A + (size_t)(mr + 32) * as + k1 + tx4);
                    pa3 = *(const float4*)(A + (size_t)(mr + 48) * as + k1 + tx4);
                    pw0 = *(const float4*)(W + (size_t)wrow0 * 1024 + k1 + tx4);
                    pw1 = *(const float4*)(W + (size_t)wrow1 * 1024 + k1 + tx4);
                }

                #pragma unroll
                for (int k = 0; k < 32; ++k) {
                    unsigned long long b0 =
                        *(const unsigned long long*)&Ws[half][k][tx4];
                    unsigned long long b1 =
                        *(const unsigned long long*)&Ws[half][k][tx4 + 2];
                    float a0 = As[half][k][ty4 + 0], a1 = As[half][k][ty4 + 1];
                    float a2 = As[half][k][ty4 + 2], a3 = As[half][k][ty4 + 3];
                    unsigned long long A0 = dup2(a0), A1 = dup2(a1);
                    unsigned long long A2 = dup2(a2), A3 = dup2(a3);
                    fma2(acc[0][0].u, A0, b0); fma2(acc[0][1].u, A0, b1);
                    fma2(acc[1][0].u, A1, b0); fma2(acc[1][1].u, A1, b1);
                    fma2(acc[2][0].u, A2, b0); fma2(acc[2][1].u, A2, b1);
                    fma2(acc[3][0].u, A3, b0); fma2(acc[3][1].u, A3, b1);
                }
            }

            // Combine the two halves' partial gates in smem
            if (half == 0) {
                #pragma unroll
                for (int r = 0; r < 4; ++r) {
                    Gs[ty4 + r][tx4 + 0] = acc[r][0].f.x;
                    Gs[ty4 + r][tx4 + 1] = acc[r][0].f.y;
                    Gs[ty4 + r][tx4 + 2] = acc[r][1].f.x;
                    Gs[ty4 + r][tx4 + 3] = acc[r][1].f.y;
                }
            }
            __syncthreads();
            if (half == 1) {
                #pragma unroll
                for (int r = 0; r < 4; ++r) {
                    Gs[ty4 + r][tx4 + 0] += acc[r][0].f.x;
                    Gs[ty4 + r][tx4 + 1] += acc[r][0].f.y;
                    Gs[ty4 + r][tx4 + 2] += acc[r][1].f.x;
                    Gs[ty4 + r][tx4 + 3] += acc[r][1].f.y;
                }
            }
            __syncthreads();

            // Pointwise LSTM update: 64 rows x 8 hidden = 512 elems, 2/thread
            #pragma unroll
            for (int q = 0; q < 2; ++q) {
                int idx = tid * 2 + q;        // 0..511
                int m = idx >> 3, hl = idx & 7;
                float gi = Gs[m][hl]      + bias_s[l][hl];
                float gf = Gs[m][8  + hl] + bias_s[l][8  + hl];
                float gg = Gs[m][16 + hl] + bias_s[l][16 + hl];
                float go = Gs[m][24 + hl] + bias_s[l][24 + hl];
                float ig = 1.f / (1.f + expf(-gi));
                float fg = 1.f / (1.f + expf(-gf));
                float gt = tanhf(gg);
                float og = 1.f / (1.f + expf(-go));
                int off = m * Hdim + n0 + hl;
                float cn = fg * cptr[off] + ig * gt;
                cptr[off] = cn;
                hout[off] = og * tanhf(cn);
            }

            grid_sync();   // publish h_t[l] / c[l] to all blocks
        }
    }
}

// out[b][o] = h_last[b] . W_fc[o] + b_fc[o]. One warp per output element.
// Final h lives in g_h[0][L-1] (t=255 has parity 1, writes buffer 0).
__global__ void fc_kernel(const float* __restrict__ Wfc,
                          const float* __restrict__ bfc,
                          float* __restrict__ out)
{
    const float* h = g_h[0][Lnum - 1];
    int warp = (blockIdx.x * blockDim.x + threadIdx.x) >> 5;
    int lane = threadIdx.x & 31;
    int b = warp >> 9;          // / 512
    int o = warp & (Odim - 1);
    const float4* hv = (const float4*)(h   + (size_t)b * Hdim);
    const float4* wv = (const float4*)(Wfc + (size_t)o * Hdim);
    float s = 0.f;
    #pragma unroll
    for (int it = 0; it < 8; ++it) {
        float4 a = hv[it * 32 + lane];
        float4 w = wv[it * 32 + lane];
        s += a.x * w.x + a.y * w.y + a.z * w.z + a.w * w.w;
    }
    #pragma unroll
    for (int off = 16; off; off >>= 1)
        s += __shfl_xor_sync(0xffffffffu, s, off);
    if (lane == 0)
        out[(size_t)b * Odim + o] = s + bfc[o];
}

extern "C" void kernel_launch(void* const* d_in, const int* in_sizes, int n_in,
                              void* d_out, int out_size)
{
    const float* x   = (const float*)d_in[0];
    const float* Wih = (const float*)d_in[1];
    const float* Whh = (const float*)d_in[2];
    const float* bih = (const float*)d_in[3];
    const float* bhh = (const float*)d_in[4];
    const float* Wfc = (const float*)d_in[5];
    const float* bfc = (const float*)d_in[6];
    float* out = (float*)d_out;

    zero_state<<<512, 1024>>>();
    lstm_persistent<<<NBLK, 256>>>(x, Wih, Whh, bih, bhh);
    fc_kernel<<<(Bsz * Odim) / 8, 256>>>(Wfc, bfc, out);   // 4096 blocks
}